// round 10
// baseline (speedup 1.0000x reference)
#include <cuda_runtime.h>
#include <cuda_bf16.h>
#include <math.h>
#include <float.h>

#define NPTS   131072
#define CF     64
#define NCLS   18
#define TILE   256
#define NTILES (NPTS / TILE)
#define VOXEL  0.04f
#define SEM_LOGIT (-1.7346010553881064f)
#define OUT_VOFF ((size_t)NCLS * NPTS * 8)

#define BND_BLKS 264
#define PRE_BLKS 248

// ---- lane-contiguous per-thread B-fragment images ----
// WA_X[nb][lane][4]  = {ks0_lo, ks0_hi, ks1_lo, ks1_hi} for n-row nb*8+g, quad t (lane=g*4+t)
// WBz_X[nb][lane][4] = {ks2_lo, ks2_hi, ks3_lo, ks3_hi}
// lo = pack(W[16ks+8h+2t][n], W[16ks+8h+2t+1][n])
__device__ __align__(16) unsigned WA_SEM[3][32][4], WBz_SEM[3][32][4];
__device__ __align__(16) unsigned WA_1[8][32][4],  WBz_1[8][32][4];
__device__ __align__(16) unsigned WA_2[8][32][4],  WBz_2[8][32][4];
__device__ __align__(16) unsigned WA_CI[NCLS][8][32][4], WBz_CI[NCLS][8][32][4];
__device__ float2 G1B1[64];
__device__ float2 G2B2[64];
__device__ float2 GCBC[NCLS][64];
__device__ float4 WO3[64];
__device__ float  THR[24];
__device__ __align__(16) float4 HEADW4[NCLS][64][2];   // [c][e][{ctr,reg0..2 | reg3..5,cls}]

__device__ int g_bmin[3] = {0x7fffffff, 0x7fffffff, 0x7fffffff};
__device__ int g_bmax[3] = {(int)0x80000000, (int)0x80000000, (int)0x80000000};

__device__ __forceinline__ unsigned packbf(float lo, float hi) {
    __nv_bfloat162 p = __floats2bfloat162_rn(lo, hi);
    return *(unsigned*)&p;
}

// decompose fragment word index -> k base
__device__ __forceinline__ int frag_k(int word, int t) {
    int ks = word >> 1, half = word & 1;
    return 16 * ks + 8 * half + 2 * t;
}

__global__ void k_pre(const int* __restrict__ coords,
                      const float* __restrict__ W_sem, const float* __restrict__ b_sem,
                      const float* __restrict__ W_o1, const float* __restrict__ g_o1,
                      const float* __restrict__ b_o1, const float* __restrict__ W_o2,
                      const float* __restrict__ g_o2, const float* __restrict__ b_o2,
                      const float* __restrict__ W_o3, const float* __restrict__ W_ci,
                      const float* __restrict__ g_ci, const float* __restrict__ b_ci,
                      const float* __restrict__ W_ctr, const float* __restrict__ W_reg,
                      const float* __restrict__ W_cls) {
    int tid = threadIdx.x;
    if (blockIdx.x < BND_BLKS) {
        __shared__ int smin[3], smax[3];
        if (tid < 3) { smin[tid] = 0x7fffffff; smax[tid] = (int)0x80000000; }
        __syncthreads();
        int l0 = 0x7fffffff, l1 = 0x7fffffff, l2 = 0x7fffffff;
        int h0 = (int)0x80000000, h1 = (int)0x80000000, h2 = (int)0x80000000;
        for (int i = blockIdx.x * 256 + tid; i < NPTS; i += BND_BLKS * 256) {
            int4 cr = __ldg((const int4*)coords + i);
            l0 = min(l0, cr.y); h0 = max(h0, cr.y);
            l1 = min(l1, cr.z); h1 = max(h1, cr.z);
            l2 = min(l2, cr.w); h2 = max(h2, cr.w);
        }
        l0 = __reduce_min_sync(0xffffffffu, l0); h0 = __reduce_max_sync(0xffffffffu, h0);
        l1 = __reduce_min_sync(0xffffffffu, l1); h1 = __reduce_max_sync(0xffffffffu, h1);
        l2 = __reduce_min_sync(0xffffffffu, l2); h2 = __reduce_max_sync(0xffffffffu, h2);
        if ((tid & 31) == 0) {
            atomicMin(&smin[0], l0); atomicMax(&smax[0], h0);
            atomicMin(&smin[1], l1); atomicMax(&smax[1], h1);
            atomicMin(&smin[2], l2); atomicMax(&smax[2], h2);
        }
        __syncthreads();
        if (tid < 3) { atomicMin(&g_bmin[tid], smin[tid]); atomicMax(&g_bmax[tid], smax[tid]); }
    } else {
        int i0 = (blockIdx.x - BND_BLKS) * 256 + tid;
        int stride = PRE_BLKS * 256;
        // sem image (3 nb rows, n padded to 24)
        for (int i = i0; i < 3 * 256; i += stride) {
            int nb = i >> 8, lane = (i >> 3) & 31, word = i & 7;
            int g = lane >> 2, t = lane & 3, n = nb * 8 + g;
            int k = frag_k(word, t);
            float w0 = (n < NCLS) ? __ldg(W_sem + k * NCLS + n) : 0.0f;
            float w1 = (n < NCLS) ? __ldg(W_sem + (k + 1) * NCLS + n) : 0.0f;
            unsigned v = packbf(w0, w1);
            if (word < 4) WA_SEM[nb][lane][word] = v; else WBz_SEM[nb][lane][word - 4] = v;
        }
        // l1 / l2 images
        for (int i = i0; i < 8 * 256; i += stride) {
            int nb = i >> 8, lane = (i >> 3) & 31, word = i & 7;
            int g = lane >> 2, t = lane & 3, n = nb * 8 + g;
            int k = frag_k(word, t);
            unsigned v1 = packbf(__ldg(W_o1 + k * 64 + n), __ldg(W_o1 + (k + 1) * 64 + n));
            unsigned v2 = packbf(__ldg(W_o2 + k * 64 + n), __ldg(W_o2 + (k + 1) * 64 + n));
            if (word < 4) { WA_1[nb][lane][word] = v1; WA_2[nb][lane][word] = v2; }
            else          { WBz_1[nb][lane][word - 4] = v1; WBz_2[nb][lane][word - 4] = v2; }
        }
        // per-class images
        for (int i = i0; i < NCLS * 8 * 256; i += stride) {
            int c = i >> 11, r = i & 2047;
            int nb = r >> 8, lane = (r >> 3) & 31, word = r & 7;
            int g = lane >> 2, t = lane & 3, n = nb * 8 + g;
            int k = frag_k(word, t);
            const float* Wc = W_ci + (size_t)c * 4096;
            unsigned v = packbf(__ldg(Wc + k * 64 + n), __ldg(Wc + (k + 1) * 64 + n));
            if (word < 4) WA_CI[c][nb][lane][word] = v; else WBz_CI[c][nb][lane][word - 4] = v;
        }
        // BN params, W_o3, thresholds, head weights
        for (int e = i0; e < 64; e += stride) {
            G1B1[e] = make_float2(__ldg(g_o1 + e), __ldg(b_o1 + e));
            G2B2[e] = make_float2(__ldg(g_o2 + e), __ldg(b_o2 + e));
            WO3[e]  = make_float4(__ldg(W_o3 + 3 * e), __ldg(W_o3 + 3 * e + 1),
                                  __ldg(W_o3 + 3 * e + 2), 0.0f);
        }
        for (int e = i0; e < 24; e += stride)
            THR[e] = (e < NCLS) ? (SEM_LOGIT - __ldg(b_sem + e)) : FLT_MAX;
        for (int i = i0; i < NCLS * 64; i += stride) {
            int c = i >> 6, e = i & 63;
            GCBC[c][e] = make_float2(__ldg(g_ci + c * CF + e), __ldg(b_ci + c * CF + e));
        }
        for (int i = i0; i < NCLS * 64 * 8; i += stride) {
            int c = i >> 9, r = i & 511;
            int e = r >> 3, j = r & 7;
            float v;
            if (j == 0)      v = __ldg(W_ctr + e);
            else if (j < 7)  v = __ldg(W_reg + e * 6 + (j - 1));
            else             v = __ldg(W_cls + e * NCLS + c);
            ((float*)&HEADW4[c][e][0])[j] = v;
        }
    }
}

__device__ __forceinline__ float eluf(float x) { return x > 0.0f ? x : (__expf(x) - 1.0f); }

__device__ __forceinline__ void mma16816(float* c, const unsigned* a, unsigned b0, unsigned b1) {
    asm volatile("mma.sync.aligned.m16n8k16.row.col.f32.bf16.bf16.f32 "
                 "{%0,%1,%2,%3}, {%4,%5,%6,%7}, {%8,%9}, {%0,%1,%2,%3};"
                 : "+f"(c[0]), "+f"(c[1]), "+f"(c[2]), "+f"(c[3])
                 : "r"(a[0]), "r"(a[1]), "r"(a[2]), "r"(a[3]), "r"(b0), "r"(b1));
}

// 4 k-blocks for one n-row, weights already in regs
__device__ __forceinline__ void mma_nrow_w(float* c, const unsigned af[4][4], uint4 wa, uint4 wb) {
    mma16816(c, af[0], wa.x, wa.y);
    mma16816(c, af[1], wa.z, wa.w);
    mma16816(c, af[2], wb.x, wb.y);
    mma16816(c, af[3], wb.z, wb.w);
}

__device__ __forceinline__ void ldfragA(const float* b0, const float* b1, int kb, unsigned* a) {
    float2 f0 = __ldg((const float2*)(b0 + kb));
    float2 f1 = __ldg((const float2*)(b1 + kb));
    float2 f2 = __ldg((const float2*)(b0 + kb + 8));
    float2 f3 = __ldg((const float2*)(b1 + kb + 8));
    a[0] = packbf(f0.x, f0.y); a[1] = packbf(f1.x, f1.y);
    a[2] = packbf(f2.x, f2.y); a[3] = packbf(f3.x, f3.y);
}

__global__ __launch_bounds__(256, 2)
void k_main(const int* __restrict__ coords, const float* __restrict__ feats,
            const float* __restrict__ b_cls, const float* __restrict__ scales,
            float* __restrict__ out)
{
    const int tid  = threadIdx.x;
    const int w    = tid >> 5;
    const int lane = tid & 31;
    const int g    = lane >> 2;
    const int t    = lane & 3;
    const int n0   = blockIdx.x * TILE;
    const int rb   = w * 32;          // warp's 32-row base (local)
    // rows: q=0..3 -> local row rb + q*8 + g ; group G = q>>1

    // ---- A fragments (2 groups of 16 rows) ----
    unsigned af[2][4][4];
#pragma unroll
    for (int G = 0; G < 2; G++) {
        const float* fb0 = feats + (size_t)(n0 + rb + G * 16 + g) * CF + 2 * t;
        const float* fb1 = fb0 + 8 * CF;
#pragma unroll
        for (int ks = 0; ks < 4; ks++) ldfragA(fb0, fb1, ks * 16, af[G][ks]);
    }

    // ---- sem GEMM -> per-row mask bits m[q] ----
    unsigned m[4] = {0u, 0u, 0u, 0u};
#pragma unroll
    for (int nb = 0; nb < 3; nb++) {
        uint4 wa = __ldg((const uint4*)&WA_SEM[nb][lane][0]);
        uint4 wb = __ldg((const uint4*)&WBz_SEM[nb][lane][0]);
        int e0 = nb * 8 + 2 * t;
        float th0 = __ldg(THR + e0), th1 = __ldg(THR + e0 + 1);
#pragma unroll
        for (int G = 0; G < 2; G++) {
            float cs[4] = {0.f, 0.f, 0.f, 0.f};
            mma_nrow_w(cs, af[G], wa, wb);
            if (cs[0] > th0) m[2 * G]     |= 1u << e0;
            if (cs[2] > th0) m[2 * G + 1] |= 1u << e0;
            if (cs[1] > th1) m[2 * G]     |= 1u << (e0 + 1);
            if (cs[3] > th1) m[2 * G + 1] |= 1u << (e0 + 1);
        }
    }
#pragma unroll
    for (int q = 0; q < 4; q++) {
        m[q] |= __shfl_xor_sync(0xffffffffu, m[q], 1);
        m[q] |= __shfl_xor_sync(0xffffffffu, m[q], 2);
    }
    const unsigned orv = __reduce_or_sync(0xffffffffu, m[0] | m[1] | m[2] | m[3]);

    // ---- l1 GEMM + BN/ELU -> l2 A-fragments in registers ----
    unsigned a2[2][4][4];
#pragma unroll
    for (int ks = 0; ks < 4; ks++) {
#pragma unroll
        for (int p = 0; p < 2; p++) {
            int nb = 2 * ks + p;
            uint4 wa = __ldg((const uint4*)&WA_1[nb][lane][0]);
            uint4 wb = __ldg((const uint4*)&WBz_1[nb][lane][0]);
            int e0 = nb * 8 + 2 * t;
            float2 gb0 = __ldg(&G1B1[e0]), gb1 = __ldg(&G1B1[e0 + 1]);
#pragma unroll
            for (int G = 0; G < 2; G++) {
                float c1[4] = {0.f, 0.f, 0.f, 0.f};
                mma_nrow_w(c1, af[G], wa, wb);
                a2[G][ks][2 * p]     = packbf(eluf(fmaf(c1[0], gb0.x, gb0.y)),
                                              eluf(fmaf(c1[1], gb1.x, gb1.y)));
                a2[G][ks][2 * p + 1] = packbf(eluf(fmaf(c1[2], gb0.x, gb0.y)),
                                              eluf(fmaf(c1[3], gb1.x, gb1.y)));
            }
        }
    }

    // ---- l2 GEMM + BN/ELU + l3 dot + voted (4 rows) ----
    {
        float ox[4] = {0.f, 0.f, 0.f, 0.f}, oy[4] = {0.f, 0.f, 0.f, 0.f}, oz[4] = {0.f, 0.f, 0.f, 0.f};
#pragma unroll
        for (int nb = 0; nb < 8; nb++) {
            uint4 wa = __ldg((const uint4*)&WA_2[nb][lane][0]);
            uint4 wb = __ldg((const uint4*)&WBz_2[nb][lane][0]);
            int e0 = nb * 8 + 2 * t;
            float2 gb0 = __ldg(&G2B2[e0]), gb1 = __ldg(&G2B2[e0 + 1]);
            float4 w0 = __ldg(&WO3[e0]), w1 = __ldg(&WO3[e0 + 1]);
#pragma unroll
            for (int G = 0; G < 2; G++) {
                float c2[4] = {0.f, 0.f, 0.f, 0.f};
                mma_nrow_w(c2, a2[G], wa, wb);
                float h00 = eluf(fmaf(c2[0], gb0.x, gb0.y)), h01 = eluf(fmaf(c2[1], gb1.x, gb1.y));
                float h10 = eluf(fmaf(c2[2], gb0.x, gb0.y)), h11 = eluf(fmaf(c2[3], gb1.x, gb1.y));
                ox[2 * G]     = fmaf(h00, w0.x, fmaf(h01, w1.x, ox[2 * G]));
                oy[2 * G]     = fmaf(h00, w0.y, fmaf(h01, w1.y, oy[2 * G]));
                oz[2 * G]     = fmaf(h00, w0.z, fmaf(h01, w1.z, oz[2 * G]));
                ox[2 * G + 1] = fmaf(h10, w0.x, fmaf(h11, w1.x, ox[2 * G + 1]));
                oy[2 * G + 1] = fmaf(h10, w0.y, fmaf(h11, w1.y, oy[2 * G + 1]));
                oz[2 * G + 1] = fmaf(h10, w0.z, fmaf(h11, w1.z, oz[2 * G + 1]));
            }
        }
#pragma unroll
        for (int s = 1; s <= 2; s <<= 1) {
#pragma unroll
            for (int q = 0; q < 4; q++) {
                ox[q] += __shfl_xor_sync(0xffffffffu, ox[q], s);
                oy[q] += __shfl_xor_sync(0xffffffffu, oy[q], s);
                oz[q] += __shfl_xor_sync(0xffffffffu, oz[q], s);
            }
        }
        if (t == 0) {
            float mn0 = (float)(g_bmin[0] - 1) * VOXEL, mx0 = (float)(g_bmax[0] + 1) * VOXEL;
            float mn1 = (float)(g_bmin[1] - 1) * VOXEL, mx1 = (float)(g_bmax[1] + 1) * VOXEL;
            float mn2 = (float)(g_bmin[2] - 1) * VOXEL, mx2 = (float)(g_bmax[2] + 1) * VOXEL;
#pragma unroll
            for (int q = 0; q < 4; q++) {
                int r = n0 + rb + q * 8 + g;
                int4 cr = __ldg((const int4*)coords + r);
                float* vp = out + OUT_VOFF + (size_t)r * 3;
                vp[0] = fminf(fmaxf(fmaf((float)cr.y, VOXEL, ox[q]), mn0), mx0);
                vp[1] = fminf(fmaxf(fmaf((float)cr.z, VOXEL, oy[q]), mn1), mx1);
                vp[2] = fminf(fmaxf(fmaf((float)cr.w, VOXEL, oz[q]), mn2), mx2);
            }
        }
    }

    // ---- per-class loop (warp-independent) ----
    for (int c = 0; c < NCLS; c++) {
        if (!((orv >> c) & 1u)) {
            // warp's 32 rows all masked: feat_c == 0 exactly -> ctr=0, reg=1, cls=b_cls
            float bc = __ldg(b_cls + c);
            float4 v = (lane & 1) ? make_float4(1.0f, 1.0f, 1.0f, bc)
                                  : make_float4(0.0f, 1.0f, 1.0f, 1.0f);
            float4* base = (float4*)(out + ((size_t)c * NPTS + n0) * 8);
            base[w * 64 + lane]      = v;
            base[w * 64 + 32 + lane] = v;
            continue;   // warp-uniform branch
        }
        // ---- slow path (fully correct; only if some of this warp's rows unmasked) ----
        float o[4][8];
#pragma unroll
        for (int q = 0; q < 4; q++)
#pragma unroll
            for (int j = 0; j < 8; j++) o[q][j] = 0.f;
        float mk[4];
#pragma unroll
        for (int q = 0; q < 4; q++) mk[q] = (float)((m[q] >> c) & 1u);
#pragma unroll
        for (int nb = 0; nb < 8; nb++) {
            uint4 wa = __ldg((const uint4*)&WA_CI[c][nb][lane][0]);
            uint4 wb = __ldg((const uint4*)&WBz_CI[c][nb][lane][0]);
            int e0 = nb * 8 + 2 * t;
            float2 gb0 = __ldg(&GCBC[c][e0]), gb1 = __ldg(&GCBC[c][e0 + 1]);
            float4 h0a = __ldg(&HEADW4[c][e0][0]),     h0b = __ldg(&HEADW4[c][e0][1]);
            float4 h1a = __ldg(&HEADW4[c][e0 + 1][0]), h1b = __ldg(&HEADW4[c][e0 + 1][1]);
            const float* he0 = (const float*)&h0a;   // 8 floats h0a..h0b contiguous in regs
            const float* he1 = (const float*)&h1a;
            float h0w[8] = {h0a.x, h0a.y, h0a.z, h0a.w, h0b.x, h0b.y, h0b.z, h0b.w};
            float h1w[8] = {h1a.x, h1a.y, h1a.z, h1a.w, h1b.x, h1b.y, h1b.z, h1b.w};
            (void)he0; (void)he1;
#pragma unroll
            for (int G = 0; G < 2; G++) {
                float cc[4] = {0.f, 0.f, 0.f, 0.f};
                mma_nrow_w(cc, af[G], wa, wb);
                float f00 = eluf(fmaf(cc[0], gb0.x, gb0.y)) * mk[2 * G];
                float f01 = eluf(fmaf(cc[1], gb1.x, gb1.y)) * mk[2 * G];
                float f10 = eluf(fmaf(cc[2], gb0.x, gb0.y)) * mk[2 * G + 1];
                float f11 = eluf(fmaf(cc[3], gb1.x, gb1.y)) * mk[2 * G + 1];
#pragma unroll
                for (int j = 0; j < 8; j++) {
                    o[2 * G][j]     = fmaf(f00, h0w[j], fmaf(f01, h1w[j], o[2 * G][j]));
                    o[2 * G + 1][j] = fmaf(f10, h0w[j], fmaf(f11, h1w[j], o[2 * G + 1][j]));
                }
            }
        }
#pragma unroll
        for (int s = 1; s <= 2; s <<= 1)
#pragma unroll
            for (int q = 0; q < 4; q++)
#pragma unroll
                for (int j = 0; j < 8; j++)
                    o[q][j] += __shfl_xor_sync(0xffffffffu, o[q][j], s);
        if (t == 0) {
            float sc = __ldg(scales + c), bc = __ldg(b_cls + c);
#pragma unroll
            for (int q = 0; q < 4; q++) {
                float* p = out + ((size_t)c * NPTS + n0 + rb + q * 8 + g) * 8;
                *(float4*)(p)     = make_float4(o[q][0], __expf(o[q][1] * sc),
                                                __expf(o[q][2] * sc), __expf(o[q][3] * sc));
                *(float4*)(p + 4) = make_float4(__expf(o[q][4] * sc), __expf(o[q][5] * sc),
                                                __expf(o[q][6] * sc), o[q][7] + bc);
            }
        }
    }
}

extern "C" void kernel_launch(void* const* d_in, const int* in_sizes, int n_in,
                              void* d_out, int out_size) {
    const int*   coords = (const int*)d_in[0];
    const float* feats  = (const float*)d_in[1];
    const float* W_sem  = (const float*)d_in[2];
    const float* b_sem  = (const float*)d_in[3];
    const float* W_o1   = (const float*)d_in[4];
    const float* g_o1   = (const float*)d_in[5];
    const float* b_o1   = (const float*)d_in[6];
    const float* W_o2   = (const float*)d_in[7];
    const float* g_o2   = (const float*)d_in[8];
    const float* b_o2   = (const float*)d_in[9];
    const float* W_o3   = (const float*)d_in[10];
    const float* W_ci   = (const float*)d_in[11];
    const float* g_ci   = (const float*)d_in[12];
    const float* b_ci   = (const float*)d_in[13];
    const float* W_ctr  = (const float*)d_in[14];
    const float* W_reg  = (const float*)d_in[15];
    const float* W_cls  = (const float*)d_in[16];
    const float* b_cls  = (const float*)d_in[17];
    const float* scales = (const float*)d_in[18];
    float* out = (float*)d_out;

    k_pre<<<BND_BLKS + PRE_BLKS, 256>>>(coords, W_sem, b_sem, W_o1, g_o1, b_o1,
                                        W_o2, g_o2, b_o2, W_o3, W_ci, g_ci, b_ci,
                                        W_ctr, W_reg, W_cls);
    k_main<<<NTILES, 256>>>(coords, feats, b_cls, scales, out);
}

// round 12
// speedup vs baseline: 1.0855x; 1.0855x over previous
#include <cuda_runtime.h>
#include <cuda_bf16.h>
#include <math.h>
#include <float.h>

#define NPTS   131072
#define CF     64
#define NCLS   18
#define VOXEL  0.04f
#define SEM_LOGIT (-1.7346010553881064f)
#define OUT_VOFF ((size_t)NCLS * NPTS * 8)

#define BND_BLKS 264
#define PRE_BLKS 120

// ---- lane-contiguous per-thread B-fragment images ----
// WA_X[nb][lane][4]  = {ks0_lo, ks0_hi, ks1_lo, ks1_hi} for n-row nb*8+g, quad t (lane=g*4+t)
// WBz_X[nb][lane][4] = {ks2_lo, ks2_hi, ks3_lo, ks3_hi}
__device__ __align__(16) unsigned WA_SEM[3][32][4], WBz_SEM[3][32][4];
__device__ __align__(16) unsigned WA_1[8][32][4],  WBz_1[8][32][4];
__device__ __align__(16) unsigned WA_2[8][32][4],  WBz_2[8][32][4];
__device__ float2 G1B1[64];
__device__ float2 G2B2[64];
__device__ float2 GCBC[NCLS][64];
__device__ float4 WO3[64];
__device__ float  THR[24];
__device__ __align__(16) float4 HEADW4[NCLS][64][2];   // [c][e][{ctr,reg0..2 | reg3..5,cls}]
__device__ unsigned g_maskarr[NPTS];

__device__ int g_bmin[3] = {0x7fffffff, 0x7fffffff, 0x7fffffff};
__device__ int g_bmax[3] = {(int)0x80000000, (int)0x80000000, (int)0x80000000};

__device__ __forceinline__ unsigned packbf(float lo, float hi) {
    __nv_bfloat162 p = __floats2bfloat162_rn(lo, hi);
    return *(unsigned*)&p;
}
__device__ __forceinline__ int frag_k(int word, int t) {
    int ks = word >> 1, half = word & 1;
    return 16 * ks + 8 * half + 2 * t;
}

__global__ void k_pre(const int* __restrict__ coords,
                      const float* __restrict__ W_sem, const float* __restrict__ b_sem,
                      const float* __restrict__ W_o1, const float* __restrict__ g_o1,
                      const float* __restrict__ b_o1, const float* __restrict__ W_o2,
                      const float* __restrict__ g_o2, const float* __restrict__ b_o2,
                      const float* __restrict__ W_o3,
                      const float* __restrict__ g_ci, const float* __restrict__ b_ci,
                      const float* __restrict__ W_ctr, const float* __restrict__ W_reg,
                      const float* __restrict__ W_cls) {
    int tid = threadIdx.x;
    if (blockIdx.x < BND_BLKS) {
        __shared__ int smin[3], smax[3];
        if (tid < 3) { smin[tid] = 0x7fffffff; smax[tid] = (int)0x80000000; }
        __syncthreads();
        int l0 = 0x7fffffff, l1 = 0x7fffffff, l2 = 0x7fffffff;
        int h0 = (int)0x80000000, h1 = (int)0x80000000, h2 = (int)0x80000000;
        for (int i = blockIdx.x * 256 + tid; i < NPTS; i += BND_BLKS * 256) {
            int4 cr = __ldg((const int4*)coords + i);
            l0 = min(l0, cr.y); h0 = max(h0, cr.y);
            l1 = min(l1, cr.z); h1 = max(h1, cr.z);
            l2 = min(l2, cr.w); h2 = max(h2, cr.w);
        }
        l0 = __reduce_min_sync(0xffffffffu, l0); h0 = __reduce_max_sync(0xffffffffu, h0);
        l1 = __reduce_min_sync(0xffffffffu, l1); h1 = __reduce_max_sync(0xffffffffu, h1);
        l2 = __reduce_min_sync(0xffffffffu, l2); h2 = __reduce_max_sync(0xffffffffu, h2);
        if ((tid & 31) == 0) {
            atomicMin(&smin[0], l0); atomicMax(&smax[0], h0);
            atomicMin(&smin[1], l1); atomicMax(&smax[1], h1);
            atomicMin(&smin[2], l2); atomicMax(&smax[2], h2);
        }
        __syncthreads();
        if (tid < 3) { atomicMin(&g_bmin[tid], smin[tid]); atomicMax(&g_bmax[tid], smax[tid]); }
    } else {
        int i0 = (blockIdx.x - BND_BLKS) * 256 + tid;
        int stride = PRE_BLKS * 256;
        for (int i = i0; i < 3 * 256; i += stride) {
            int nb = i >> 8, lane = (i >> 3) & 31, word = i & 7;
            int g = lane >> 2, t = lane & 3, n = nb * 8 + g;
            int k = frag_k(word, t);
            float w0 = (n < NCLS) ? __ldg(W_sem + k * NCLS + n) : 0.0f;
            float w1 = (n < NCLS) ? __ldg(W_sem + (k + 1) * NCLS + n) : 0.0f;
            unsigned v = packbf(w0, w1);
            if (word < 4) WA_SEM[nb][lane][word] = v; else WBz_SEM[nb][lane][word - 4] = v;
        }
        for (int i = i0; i < 8 * 256; i += stride) {
            int nb = i >> 8, lane = (i >> 3) & 31, word = i & 7;
            int g = lane >> 2, t = lane & 3, n = nb * 8 + g;
            int k = frag_k(word, t);
            unsigned v1 = packbf(__ldg(W_o1 + k * 64 + n), __ldg(W_o1 + (k + 1) * 64 + n));
            unsigned v2 = packbf(__ldg(W_o2 + k * 64 + n), __ldg(W_o2 + (k + 1) * 64 + n));
            if (word < 4) { WA_1[nb][lane][word] = v1; WA_2[nb][lane][word] = v2; }
            else          { WBz_1[nb][lane][word - 4] = v1; WBz_2[nb][lane][word - 4] = v2; }
        }
        for (int e = i0; e < 64; e += stride) {
            G1B1[e] = make_float2(__ldg(g_o1 + e), __ldg(b_o1 + e));
            G2B2[e] = make_float2(__ldg(g_o2 + e), __ldg(b_o2 + e));
            WO3[e]  = make_float4(__ldg(W_o3 + 3 * e), __ldg(W_o3 + 3 * e + 1),
                                  __ldg(W_o3 + 3 * e + 2), 0.0f);
        }
        for (int e = i0; e < 24; e += stride)
            THR[e] = (e < NCLS) ? (SEM_LOGIT - __ldg(b_sem + e)) : FLT_MAX;
        for (int i = i0; i < NCLS * 64; i += stride) {
            int c = i >> 6, e = i & 63;
            GCBC[c][e] = make_float2(__ldg(g_ci + c * CF + e), __ldg(b_ci + c * CF + e));
        }
        for (int i = i0; i < NCLS * 64 * 8; i += stride) {
            int c = i >> 9, r = i & 511;
            int e = r >> 3, j = r & 7;
            float v;
            if (j == 0)      v = __ldg(W_ctr + e);
            else if (j < 7)  v = __ldg(W_reg + e * 6 + (j - 1));
            else             v = __ldg(W_cls + e * NCLS + c);
            ((float*)&HEADW4[c][e][0])[j] = v;
        }
    }
}

__device__ __forceinline__ float eluf(float x) { return x > 0.0f ? x : (__expf(x) - 1.0f); }

__device__ __forceinline__ void mma16816(float* c, const unsigned* a, unsigned b0, unsigned b1) {
    asm volatile("mma.sync.aligned.m16n8k16.row.col.f32.bf16.bf16.f32 "
                 "{%0,%1,%2,%3}, {%4,%5,%6,%7}, {%8,%9}, {%0,%1,%2,%3};"
                 : "+f"(c[0]), "+f"(c[1]), "+f"(c[2]), "+f"(c[3])
                 : "r"(a[0]), "r"(a[1]), "r"(a[2]), "r"(a[3]), "r"(b0), "r"(b1));
}
__device__ __forceinline__ void mma_nrow_w(float* c, const unsigned af[4][4], uint4 wa, uint4 wb) {
    mma16816(c, af[0], wa.x, wa.y);
    mma16816(c, af[1], wa.z, wa.w);
    mma16816(c, af[2], wb.x, wb.y);
    mma16816(c, af[3], wb.z, wb.w);
}
__device__ __forceinline__ void ldfragA(const float* b0, const float* b1, int kb, unsigned* a) {
    float2 f0 = __ldg((const float2*)(b0 + kb));
    float2 f1 = __ldg((const float2*)(b1 + kb));
    float2 f2 = __ldg((const float2*)(b0 + kb + 8));
    float2 f3 = __ldg((const float2*)(b1 + kb + 8));
    a[0] = packbf(f0.x, f0.y); a[1] = packbf(f1.x, f1.y);
    a[2] = packbf(f2.x, f2.y); a[3] = packbf(f3.x, f3.y);
}

// ---- compute kernel: sem mask -> g_maskarr, offset MLP -> voted ----
__global__ __launch_bounds__(256, 3)
void k_ab(const int* __restrict__ coords, const float* __restrict__ feats,
          float* __restrict__ out)
{
    const int tid  = threadIdx.x;
    const int w    = tid >> 5;
    const int lane = tid & 31;
    const int g    = lane >> 2;
    const int t    = lane & 3;
    const int r0   = blockIdx.x * 128 + w * 16 + g;   // this thread's first row
    const int r1   = r0 + 8;

    // ---- A fragments straight from global fp32 feats ----
    unsigned af[4][4];
    {
        const float* fb0 = feats + (size_t)r0 * CF + 2 * t;
        const float* fb1 = fb0 + 8 * CF;
#pragma unroll
        for (int ks = 0; ks < 4; ks++) ldfragA(fb0, fb1, ks * 16, af[ks]);
    }

    // ---- sem GEMM -> per-row mask bits -> g_maskarr ----
    unsigned m0 = 0, m1 = 0;
#pragma unroll
    for (int nb = 0; nb < 3; nb++) {
        uint4 wa = __ldg((const uint4*)&WA_SEM[nb][lane][0]);
        uint4 wb = __ldg((const uint4*)&WBz_SEM[nb][lane][0]);
        float cs[4] = {0.f, 0.f, 0.f, 0.f};
        mma_nrow_w(cs, af, wa, wb);
        int e0 = nb * 8 + 2 * t;
        float th0 = __ldg(THR + e0), th1 = __ldg(THR + e0 + 1);
        if (cs[0] > th0) m0 |= 1u << e0;
        if (cs[2] > th0) m1 |= 1u << e0;
        if (cs[1] > th1) m0 |= 1u << (e0 + 1);
        if (cs[3] > th1) m1 |= 1u << (e0 + 1);
    }
    m0 |= __shfl_xor_sync(0xffffffffu, m0, 1); m0 |= __shfl_xor_sync(0xffffffffu, m0, 2);
    m1 |= __shfl_xor_sync(0xffffffffu, m1, 1); m1 |= __shfl_xor_sync(0xffffffffu, m1, 2);
    if (t == 0) { g_maskarr[r0] = m0; g_maskarr[r1] = m1; }

    // ---- l1 GEMM + BN/ELU -> l2 A-fragments in registers ----
    unsigned a2[4][4];
#pragma unroll
    for (int ks = 0; ks < 4; ks++) {
#pragma unroll
        for (int p = 0; p < 2; p++) {
            int nb = 2 * ks + p;
            uint4 wa = __ldg((const uint4*)&WA_1[nb][lane][0]);
            uint4 wb = __ldg((const uint4*)&WBz_1[nb][lane][0]);
            float c1[4] = {0.f, 0.f, 0.f, 0.f};
            mma_nrow_w(c1, af, wa, wb);
            int e0 = nb * 8 + 2 * t;
            float2 gb0 = __ldg(&G1B1[e0]), gb1 = __ldg(&G1B1[e0 + 1]);
            a2[ks][2 * p]     = packbf(eluf(fmaf(c1[0], gb0.x, gb0.y)),
                                       eluf(fmaf(c1[1], gb1.x, gb1.y)));
            a2[ks][2 * p + 1] = packbf(eluf(fmaf(c1[2], gb0.x, gb0.y)),
                                       eluf(fmaf(c1[3], gb1.x, gb1.y)));
        }
    }

    // ---- l2 GEMM + BN/ELU + l3 dot + voted ----
    float o0x = 0.f, o0y = 0.f, o0z = 0.f, o1x = 0.f, o1y = 0.f, o1z = 0.f;
#pragma unroll
    for (int nb = 0; nb < 8; nb++) {
        uint4 wa = __ldg((const uint4*)&WA_2[nb][lane][0]);
        uint4 wb = __ldg((const uint4*)&WBz_2[nb][lane][0]);
        float c2[4] = {0.f, 0.f, 0.f, 0.f};
        mma_nrow_w(c2, a2, wa, wb);
        int e0 = nb * 8 + 2 * t;
        float2 gb0 = __ldg(&G2B2[e0]), gb1 = __ldg(&G2B2[e0 + 1]);
        float h00 = eluf(fmaf(c2[0], gb0.x, gb0.y)), h01 = eluf(fmaf(c2[1], gb1.x, gb1.y));
        float h10 = eluf(fmaf(c2[2], gb0.x, gb0.y)), h11 = eluf(fmaf(c2[3], gb1.x, gb1.y));
        float4 w0 = __ldg(&WO3[e0]), w1 = __ldg(&WO3[e0 + 1]);
        o0x = fmaf(h00, w0.x, fmaf(h01, w1.x, o0x));
        o0y = fmaf(h00, w0.y, fmaf(h01, w1.y, o0y));
        o0z = fmaf(h00, w0.z, fmaf(h01, w1.z, o0z));
        o1x = fmaf(h10, w0.x, fmaf(h11, w1.x, o1x));
        o1y = fmaf(h10, w0.y, fmaf(h11, w1.y, o1y));
        o1z = fmaf(h10, w0.z, fmaf(h11, w1.z, o1z));
    }
#pragma unroll
    for (int s = 1; s <= 2; s <<= 1) {
        o0x += __shfl_xor_sync(0xffffffffu, o0x, s);
        o0y += __shfl_xor_sync(0xffffffffu, o0y, s);
        o0z += __shfl_xor_sync(0xffffffffu, o0z, s);
        o1x += __shfl_xor_sync(0xffffffffu, o1x, s);
        o1y += __shfl_xor_sync(0xffffffffu, o1y, s);
        o1z += __shfl_xor_sync(0xffffffffu, o1z, s);
    }
    if (t == 0) {
        float mn0 = (float)(g_bmin[0] - 1) * VOXEL, mx0 = (float)(g_bmax[0] + 1) * VOXEL;
        float mn1 = (float)(g_bmin[1] - 1) * VOXEL, mx1 = (float)(g_bmax[1] + 1) * VOXEL;
        float mn2 = (float)(g_bmin[2] - 1) * VOXEL, mx2 = (float)(g_bmax[2] + 1) * VOXEL;
        int4 c0 = __ldg((const int4*)coords + r0);
        int4 c1c = __ldg((const int4*)coords + r1);
        float* v0 = out + OUT_VOFF + (size_t)r0 * 3;
        float* v1 = out + OUT_VOFF + (size_t)r1 * 3;
        v0[0] = fminf(fmaxf(fmaf((float)c0.y, VOXEL, o0x), mn0), mx0);
        v0[1] = fminf(fmaxf(fmaf((float)c0.z, VOXEL, o0y), mn1), mx1);
        v0[2] = fminf(fmaxf(fmaf((float)c0.w, VOXEL, o0z), mn2), mx2);
        v1[0] = fminf(fmaxf(fmaf((float)c1c.y, VOXEL, o1x), mn0), mx0);
        v1[1] = fminf(fmaxf(fmaf((float)c1c.z, VOXEL, o1y), mn1), mx1);
        v1[2] = fminf(fmaxf(fmaf((float)c1c.w, VOXEL, o1z), mn2), mx2);
    }
}

// ---- streaming kernel: per-class outputs from mask ----
__global__ __launch_bounds__(256, 4)
void k_c(const float* __restrict__ feats, const float* __restrict__ W_ci,
         const float* __restrict__ b_cls, const float* __restrict__ scales,
         float* __restrict__ out)
{
    const int tid  = threadIdx.x;
    const int w    = tid >> 5;
    const int lane = tid & 31;
    const int r0   = blockIdx.x * 256 + w * 32;     // warp covers 32 rows
    const int row  = r0 + lane;

    const unsigned mw  = __ldg(g_maskarr + row);
    const unsigned worv = __reduce_or_sync(0xffffffffu, mw);

    for (int c = 0; c < NCLS; c++) {
        float4* base4 = (float4*)(out + ((size_t)c * NPTS + r0) * 8);
        if (!((worv >> c) & 1u)) {
            // warp's 32 rows all masked: feat_c == 0 exactly -> ctr=0, reg=exp(0)=1, cls=b_cls
            float bc = __ldg(b_cls + c);
            float4 v = (lane & 1) ? make_float4(1.0f, 1.0f, 1.0f, bc)
                                  : make_float4(0.0f, 1.0f, 1.0f, 1.0f);
            base4[lane]      = v;
            base4[lane + 32] = v;
            continue;   // warp-uniform branch
        }
        // ---- slow path: exact fp32 SIMT per-row (only when some row unmasked) ----
        float o[8];
#pragma unroll
        for (int j = 0; j < 8; j++) o[j] = 0.f;
        if ((mw >> c) & 1u) {
            const float* fr = feats + (size_t)row * CF;
            const float* Wc = W_ci + (size_t)c * 4096;
            for (int ec = 0; ec < 8; ec++) {
                int e0 = ec * 8;
                float acc[8];
#pragma unroll
                for (int j = 0; j < 8; j++) acc[j] = 0.f;
                for (int k = 0; k < CF; k++) {
                    float f = __ldg(fr + k);
                    const float* wk = Wc + k * 64 + e0;
#pragma unroll
                    for (int j = 0; j < 8; j++) acc[j] = fmaf(f, __ldg(wk + j), acc[j]);
                }
#pragma unroll
                for (int j = 0; j < 8; j++) {
                    float2 gb = __ldg(&GCBC[c][e0 + j]);
                    float fc = eluf(fmaf(acc[j], gb.x, gb.y));
                    float4 ha = __ldg(&HEADW4[c][e0 + j][0]);
                    float4 hb = __ldg(&HEADW4[c][e0 + j][1]);
                    o[0] = fmaf(fc, ha.x, o[0]); o[1] = fmaf(fc, ha.y, o[1]);
                    o[2] = fmaf(fc, ha.z, o[2]); o[3] = fmaf(fc, ha.w, o[3]);
                    o[4] = fmaf(fc, hb.x, o[4]); o[5] = fmaf(fc, hb.y, o[5]);
                    o[6] = fmaf(fc, hb.z, o[6]); o[7] = fmaf(fc, hb.w, o[7]);
                }
            }
        }
        float sc = __ldg(scales + c), bc = __ldg(b_cls + c);
        float* p = out + ((size_t)c * NPTS + row) * 8;
        *(float4*)(p)     = make_float4(o[0], __expf(o[1] * sc),
                                        __expf(o[2] * sc), __expf(o[3] * sc));
        *(float4*)(p + 4) = make_float4(__expf(o[4] * sc), __expf(o[5] * sc),
                                        __expf(o[6] * sc), o[7] + bc);
    }
}

extern "C" void kernel_launch(void* const* d_in, const int* in_sizes, int n_in,
                              void* d_out, int out_size) {
    const int*   coords = (const int*)d_in[0];
    const float* feats  = (const float*)d_in[1];
    const float* W_sem  = (const float*)d_in[2];
    const float* b_sem  = (const float*)d_in[3];
    const float* W_o1   = (const float*)d_in[4];
    const float* g_o1   = (const float*)d_in[5];
    const float* b_o1   = (const float*)d_in[6];
    const float* W_o2   = (const float*)d_in[7];
    const float* g_o2   = (const float*)d_in[8];
    const float* b_o2   = (const float*)d_in[9];
    const float* W_o3   = (const float*)d_in[10];
    const float* W_ci   = (const float*)d_in[11];
    const float* g_ci   = (const float*)d_in[12];
    const float* b_ci   = (const float*)d_in[13];
    const float* W_ctr  = (const float*)d_in[14];
    const float* W_reg  = (const float*)d_in[15];
    const float* W_cls  = (const float*)d_in[16];
    const float* b_cls  = (const float*)d_in[17];
    const float* scales = (const float*)d_in[18];
    float* out = (float*)d_out;

    k_pre<<<BND_BLKS + PRE_BLKS, 256>>>(coords, W_sem, b_sem, W_o1, g_o1, b_o1,
                                        W_o2, g_o2, b_o2, W_o3, g_ci, b_ci,
                                        W_ctr, W_reg, W_cls);
    k_ab<<<NPTS / 128, 256>>>(coords, feats, out);
    k_c<<<NPTS / 256, 256>>>(feats, W_ci, b_cls, scales, out);
}

// round 14
// speedup vs baseline: 1.0901x; 1.0043x over previous
#include <cuda_runtime.h>
#include <cuda_bf16.h>
#include <math.h>
#include <float.h>

#define NPTS   131072
#define CF     64
#define NCLS   18
#define VOXEL  0.04f
#define SEM_LOGIT (-1.7346010553881064f)
#define OUT_VOFF ((size_t)NCLS * NPTS * 8)

// ---- lane-contiguous per-thread B-fragment images ----
__device__ __align__(16) unsigned WA_SEM[3][32][4], WBz_SEM[3][32][4];
__device__ __align__(16) unsigned WA_1[8][32][4],  WBz_1[8][32][4];
__device__ __align__(16) unsigned WA_2[8][32][4],  WBz_2[8][32][4];
__device__ float2 G1B1[64];
__device__ float2 G2B2[64];
__device__ float2 GCBC[NCLS][64];
__device__ float4 WO3[64];
__device__ float  THR[24];
__device__ __align__(16) float4 HEADW4[NCLS][64][2];
__device__ unsigned g_maskarr[NPTS];

__device__ int g_bmin[3] = {0x7fffffff, 0x7fffffff, 0x7fffffff};
__device__ int g_bmax[3] = {(int)0x80000000, (int)0x80000000, (int)0x80000000};

__device__ __forceinline__ unsigned packbf(float lo, float hi) {
    __nv_bfloat162 p = __floats2bfloat162_rn(lo, hi);
    return *(unsigned*)&p;
}
__device__ __forceinline__ int frag_k(int word, int t) {
    int ks = word >> 1, half = word & 1;
    return 16 * ks + 8 * half + 2 * t;
}

// ---- prep-only kernel (small, every loop <= 1 iter/thread) ----
__global__ __launch_bounds__(256)
void k_pre(const float* __restrict__ W_sem, const float* __restrict__ b_sem,
           const float* __restrict__ W_o1, const float* __restrict__ g_o1,
           const float* __restrict__ b_o1, const float* __restrict__ W_o2,
           const float* __restrict__ g_o2, const float* __restrict__ b_o2,
           const float* __restrict__ W_o3,
           const float* __restrict__ g_ci, const float* __restrict__ b_ci,
           const float* __restrict__ W_ctr, const float* __restrict__ W_reg,
           const float* __restrict__ W_cls) {
    int i0 = blockIdx.x * 256 + threadIdx.x;
    int stride = gridDim.x * 256;
    for (int i = i0; i < 3 * 256; i += stride) {
        int nb = i >> 8, lane = (i >> 3) & 31, word = i & 7;
        int g = lane >> 2, t = lane & 3, n = nb * 8 + g;
        int k = frag_k(word, t);
        float w0 = (n < NCLS) ? __ldg(W_sem + k * NCLS + n) : 0.0f;
        float w1 = (n < NCLS) ? __ldg(W_sem + (k + 1) * NCLS + n) : 0.0f;
        unsigned v = packbf(w0, w1);
        if (word < 4) WA_SEM[nb][lane][word] = v; else WBz_SEM[nb][lane][word - 4] = v;
    }
    for (int i = i0; i < 8 * 256; i += stride) {
        int nb = i >> 8, lane = (i >> 3) & 31, word = i & 7;
        int g = lane >> 2, t = lane & 3, n = nb * 8 + g;
        int k = frag_k(word, t);
        unsigned v1 = packbf(__ldg(W_o1 + k * 64 + n), __ldg(W_o1 + (k + 1) * 64 + n));
        unsigned v2 = packbf(__ldg(W_o2 + k * 64 + n), __ldg(W_o2 + (k + 1) * 64 + n));
        if (word < 4) { WA_1[nb][lane][word] = v1; WA_2[nb][lane][word] = v2; }
        else          { WBz_1[nb][lane][word - 4] = v1; WBz_2[nb][lane][word - 4] = v2; }
    }
    for (int e = i0; e < 64; e += stride) {
        G1B1[e] = make_float2(__ldg(g_o1 + e), __ldg(b_o1 + e));
        G2B2[e] = make_float2(__ldg(g_o2 + e), __ldg(b_o2 + e));
        WO3[e]  = make_float4(__ldg(W_o3 + 3 * e), __ldg(W_o3 + 3 * e + 1),
                              __ldg(W_o3 + 3 * e + 2), 0.0f);
    }
    for (int e = i0; e < 24; e += stride)
        THR[e] = (e < NCLS) ? (SEM_LOGIT - __ldg(b_sem + e)) : FLT_MAX;
    for (int i = i0; i < NCLS * 64; i += stride) {
        int c = i >> 6, e = i & 63;
        GCBC[c][e] = make_float2(__ldg(g_ci + c * CF + e), __ldg(b_ci + c * CF + e));
    }
    for (int i = i0; i < NCLS * 64 * 8; i += stride) {
        int c = i >> 9, r = i & 511;
        int e = r >> 3, j = r & 7;
        float v;
        if (j == 0)      v = __ldg(W_ctr + e);
        else if (j < 7)  v = __ldg(W_reg + e * 6 + (j - 1));
        else             v = __ldg(W_cls + e * NCLS + c);
        ((float*)&HEADW4[c][e][0])[j] = v;
    }
}

__device__ __forceinline__ float eluf(float x) { return x > 0.0f ? x : (__expf(x) - 1.0f); }

__device__ __forceinline__ void mma16816(float* c, const unsigned* a, unsigned b0, unsigned b1) {
    asm volatile("mma.sync.aligned.m16n8k16.row.col.f32.bf16.bf16.f32 "
                 "{%0,%1,%2,%3}, {%4,%5,%6,%7}, {%8,%9}, {%0,%1,%2,%3};"
                 : "+f"(c[0]), "+f"(c[1]), "+f"(c[2]), "+f"(c[3])
                 : "r"(a[0]), "r"(a[1]), "r"(a[2]), "r"(a[3]), "r"(b0), "r"(b1));
}
__device__ __forceinline__ void mma_nrow_w(float* c, const unsigned af[4][4], uint4 wa, uint4 wb) {
    mma16816(c, af[0], wa.x, wa.y);
    mma16816(c, af[1], wa.z, wa.w);
    mma16816(c, af[2], wb.x, wb.y);
    mma16816(c, af[3], wb.z, wb.w);
}

#define PITCH 36   // smem row pitch in 4B words (bank = 4g+t, conflict-free frag loads)

// ---- compute kernel: bounds + mask + MLP -> unclipped voted ----
__global__ __launch_bounds__(128, 4)
void k_ab(const int* __restrict__ coords, const float* __restrict__ feats,
          float* __restrict__ out)
{
    __shared__ unsigned s_stage[4][32 * PITCH];
    const int tid  = threadIdx.x;
    const int w    = tid >> 5;
    const int lane = tid & 31;
    const int g    = lane >> 2;
    const int t    = lane & 3;
    const int rb   = blockIdx.x * 128 + w * 32;   // warp covers 32 rows

    // ---- bounds contribution (lane-per-row, warp reduce, global RED) ----
    {
        int4 cr = __ldg((const int4*)coords + rb + lane);
        int l0 = __reduce_min_sync(0xffffffffu, cr.y), h0 = __reduce_max_sync(0xffffffffu, cr.y);
        int l1 = __reduce_min_sync(0xffffffffu, cr.z), h1 = __reduce_max_sync(0xffffffffu, cr.z);
        int l2 = __reduce_min_sync(0xffffffffu, cr.w), h2 = __reduce_max_sync(0xffffffffu, cr.w);
        if (lane == 0) {
            atomicMin(&g_bmin[0], l0); atomicMax(&g_bmax[0], h0);
            atomicMin(&g_bmin[1], l1); atomicMax(&g_bmax[1], h1);
            atomicMin(&g_bmin[2], l2); atomicMax(&g_bmax[2], h2);
        }
    }

    // ---- stage warp's 32 rows -> bf16 smem (coalesced LDG.128) ----
    unsigned* st = s_stage[w];
    {
        const float4* base = (const float4*)(feats + (size_t)rb * CF);
#pragma unroll
        for (int it = 0; it < 16; it++) {
            int i = it * 32 + lane;
            float4 v = __ldg(base + i);
            int r = i >> 4, c = i & 15;
            st[r * PITCH + 2 * c]     = packbf(v.x, v.y);
            st[r * PITCH + 2 * c + 1] = packbf(v.z, v.w);
        }
    }
    __syncwarp();

    // ---- A fragments via conflict-free LDS.32 ----
    unsigned af[2][4][4];
#pragma unroll
    for (int G = 0; G < 2; G++) {
        int ra = (G * 16 + g) * PITCH, rc = (G * 16 + g + 8) * PITCH;
#pragma unroll
        for (int ks = 0; ks < 4; ks++) {
            af[G][ks][0] = st[ra + 8 * ks + t];
            af[G][ks][1] = st[rc + 8 * ks + t];
            af[G][ks][2] = st[ra + 8 * ks + 4 + t];
            af[G][ks][3] = st[rc + 8 * ks + 4 + t];
        }
    }

    // ---- sem GEMM -> mask bits -> g_maskarr ----
    unsigned m[4] = {0u, 0u, 0u, 0u};
#pragma unroll
    for (int nb = 0; nb < 3; nb++) {
        uint4 wa = __ldg((const uint4*)&WA_SEM[nb][lane][0]);
        uint4 wb = __ldg((const uint4*)&WBz_SEM[nb][lane][0]);
        int e0 = nb * 8 + 2 * t;
        float th0 = __ldg(THR + e0), th1 = __ldg(THR + e0 + 1);
#pragma unroll
        for (int G = 0; G < 2; G++) {
            float cs[4] = {0.f, 0.f, 0.f, 0.f};
            mma_nrow_w(cs, af[G], wa, wb);
            if (cs[0] > th0) m[2 * G]     |= 1u << e0;
            if (cs[2] > th0) m[2 * G + 1] |= 1u << e0;
            if (cs[1] > th1) m[2 * G]     |= 1u << (e0 + 1);
            if (cs[3] > th1) m[2 * G + 1] |= 1u << (e0 + 1);
        }
    }
#pragma unroll
    for (int q = 0; q < 4; q++) {
        m[q] |= __shfl_xor_sync(0xffffffffu, m[q], 1);
        m[q] |= __shfl_xor_sync(0xffffffffu, m[q], 2);
    }
    if (t == 0) {
#pragma unroll
        for (int q = 0; q < 4; q++)
            g_maskarr[rb + (q >> 1) * 16 + (q & 1) * 8 + g] = m[q];
    }

    // ---- l1 GEMM + BN/ELU -> l2 A-fragments in registers ----
    unsigned a2[2][4][4];
#pragma unroll
    for (int ks = 0; ks < 4; ks++) {
#pragma unroll
        for (int p = 0; p < 2; p++) {
            int nb = 2 * ks + p;
            uint4 wa = __ldg((const uint4*)&WA_1[nb][lane][0]);
            uint4 wb = __ldg((const uint4*)&WBz_1[nb][lane][0]);
            int e0 = nb * 8 + 2 * t;
            float2 gb0 = __ldg(&G1B1[e0]), gb1 = __ldg(&G1B1[e0 + 1]);
#pragma unroll
            for (int G = 0; G < 2; G++) {
                float c1[4] = {0.f, 0.f, 0.f, 0.f};
                mma_nrow_w(c1, af[G], wa, wb);
                a2[G][ks][2 * p]     = packbf(eluf(fmaf(c1[0], gb0.x, gb0.y)),
                                              eluf(fmaf(c1[1], gb1.x, gb1.y)));
                a2[G][ks][2 * p + 1] = packbf(eluf(fmaf(c1[2], gb0.x, gb0.y)),
                                              eluf(fmaf(c1[3], gb1.x, gb1.y)));
            }
        }
    }

    // ---- l2 GEMM + BN/ELU + l3 dot -> UNCLIPPED voted (clip in k_c) ----
    float ox[4] = {0.f, 0.f, 0.f, 0.f}, oy[4] = {0.f, 0.f, 0.f, 0.f}, oz[4] = {0.f, 0.f, 0.f, 0.f};
#pragma unroll
    for (int nb = 0; nb < 8; nb++) {
        uint4 wa = __ldg((const uint4*)&WA_2[nb][lane][0]);
        uint4 wb = __ldg((const uint4*)&WBz_2[nb][lane][0]);
        int e0 = nb * 8 + 2 * t;
        float2 gb0 = __ldg(&G2B2[e0]), gb1 = __ldg(&G2B2[e0 + 1]);
        float4 w0 = __ldg(&WO3[e0]), w1 = __ldg(&WO3[e0 + 1]);
#pragma unroll
        for (int G = 0; G < 2; G++) {
            float c2[4] = {0.f, 0.f, 0.f, 0.f};
            mma_nrow_w(c2, a2[G], wa, wb);
            float h00 = eluf(fmaf(c2[0], gb0.x, gb0.y)), h01 = eluf(fmaf(c2[1], gb1.x, gb1.y));
            float h10 = eluf(fmaf(c2[2], gb0.x, gb0.y)), h11 = eluf(fmaf(c2[3], gb1.x, gb1.y));
            ox[2 * G]     = fmaf(h00, w0.x, fmaf(h01, w1.x, ox[2 * G]));
            oy[2 * G]     = fmaf(h00, w0.y, fmaf(h01, w1.y, oy[2 * G]));
            oz[2 * G]     = fmaf(h00, w0.z, fmaf(h01, w1.z, oz[2 * G]));
            ox[2 * G + 1] = fmaf(h10, w0.x, fmaf(h11, w1.x, ox[2 * G + 1]));
            oy[2 * G + 1] = fmaf(h10, w0.y, fmaf(h11, w1.y, oy[2 * G + 1]));
            oz[2 * G + 1] = fmaf(h10, w0.z, fmaf(h11, w1.z, oz[2 * G + 1]));
        }
    }
#pragma unroll
    for (int s = 1; s <= 2; s <<= 1) {
#pragma unroll
        for (int q = 0; q < 4; q++) {
            ox[q] += __shfl_xor_sync(0xffffffffu, ox[q], s);
            oy[q] += __shfl_xor_sync(0xffffffffu, oy[q], s);
            oz[q] += __shfl_xor_sync(0xffffffffu, oz[q], s);
        }
    }
    if (t == 0) {
#pragma unroll
        for (int q = 0; q < 4; q++) {
            int r = rb + (q >> 1) * 16 + (q & 1) * 8 + g;
            int4 cr = __ldg((const int4*)coords + r);
            float* vp = out + OUT_VOFF + (size_t)r * 3;
            vp[0] = fmaf((float)cr.y, VOXEL, ox[q]);
            vp[1] = fmaf((float)cr.z, VOXEL, oy[q]);
            vp[2] = fmaf((float)cr.w, VOXEL, oz[q]);
        }
    }
}

// ---- streaming kernel: voted clip + per-class outputs ----
__global__ __launch_bounds__(256, 4)
void k_c(const float* __restrict__ feats, const float* __restrict__ W_ci,
         const float* __restrict__ b_cls, const float* __restrict__ scales,
         float* __restrict__ out)
{
    const int tid  = threadIdx.x;
    const int w    = tid >> 5;
    const int lane = tid & 31;
    const int r0   = blockIdx.x * 256 + w * 32;
    const int row  = r0 + lane;

    // ---- clip voted for this warp's 32 rows (bounds now final) ----
    {
        float mn0 = (float)(g_bmin[0] - 1) * VOXEL, mx0 = (float)(g_bmax[0] + 1) * VOXEL;
        float mn1 = (float)(g_bmin[1] - 1) * VOXEL, mx1 = (float)(g_bmax[1] + 1) * VOXEL;
        float mn2 = (float)(g_bmin[2] - 1) * VOXEL, mx2 = (float)(g_bmax[2] + 1) * VOXEL;
        float* vp = out + OUT_VOFF + (size_t)r0 * 3;
#pragma unroll
        for (int j = 0; j < 3; j++) {
            int idx = j * 32 + lane;
            int dim = idx % 3;
            float v = vp[idx];
            float lo = (dim == 0) ? mn0 : ((dim == 1) ? mn1 : mn2);
            float hi = (dim == 0) ? mx0 : ((dim == 1) ? mx1 : mx2);
            vp[idx] = fminf(fmaxf(v, lo), hi);
        }
    }

    const unsigned mw   = __ldg(g_maskarr + row);
    const unsigned worv = __reduce_or_sync(0xffffffffu, mw);

    for (int c = 0; c < NCLS; c++) {
        float4* base4 = (float4*)(out + ((size_t)c * NPTS + r0) * 8);
        if (!((worv >> c) & 1u)) {
            // warp's 32 rows all masked: feat_c == 0 exactly -> ctr=0, reg=exp(0)=1, cls=b_cls
            float bc = __ldg(b_cls + c);
            float4 v = (lane & 1) ? make_float4(1.0f, 1.0f, 1.0f, bc)
                                  : make_float4(0.0f, 1.0f, 1.0f, 1.0f);
            base4[lane]      = v;
            base4[lane + 32] = v;
            continue;   // warp-uniform branch
        }
        // ---- slow path: exact fp32 SIMT per-row ----
        float o[8];
#pragma unroll
        for (int j = 0; j < 8; j++) o[j] = 0.f;
        if ((mw >> c) & 1u) {
            const float* fr = feats + (size_t)row * CF;
            const float* Wc = W_ci + (size_t)c * 4096;
            for (int ec = 0; ec < 8; ec++) {
                int e0 = ec * 8;
                float acc[8];
#pragma unroll
                for (int j = 0; j < 8; j++) acc[j] = 0.f;
                for (int k = 0; k < CF; k++) {
                    float f = __ldg(fr + k);
                    const float* wk = Wc + k * 64 + e0;
#pragma unroll
                    for (int j = 0; j < 8; j++) acc[j] = fmaf(f, __ldg(wk + j), acc[j]);
                }
#pragma unroll
                for (int j = 0; j < 8; j++) {
                    float2 gb = __ldg(&GCBC[c][e0 + j]);
                    float fc = eluf(fmaf(acc[j], gb.x, gb.y));
                    float4 ha = __ldg(&HEADW4[c][e0 + j][0]);
                    float4 hb = __ldg(&HEADW4[c][e0 + j][1]);
                    o[0] = fmaf(fc, ha.x, o[0]); o[1] = fmaf(fc, ha.y, o[1]);
                    o[2] = fmaf(fc, ha.z, o[2]); o[3] = fmaf(fc, ha.w, o[3]);
                    o[4] = fmaf(fc, hb.x, o[4]); o[5] = fmaf(fc, hb.y, o[5]);
                    o[6] = fmaf(fc, hb.z, o[6]); o[7] = fmaf(fc, hb.w, o[7]);
                }
            }
        }
        float sc = __ldg(scales + c), bc = __ldg(b_cls + c);
        float* p = out + ((size_t)c * NPTS + row) * 8;
        *(float4*)(p)     = make_float4(o[0], __expf(o[1] * sc),
                                        __expf(o[2] * sc), __expf(o[3] * sc));
        *(float4*)(p + 4) = make_float4(__expf(o[4] * sc), __expf(o[5] * sc),
                                        __expf(o[6] * sc), o[7] + bc);
    }
}

extern "C" void kernel_launch(void* const* d_in, const int* in_sizes, int n_in,
                              void* d_out, int out_size) {
    const int*   coords = (const int*)d_in[0];
    const float* feats  = (const float*)d_in[1];
    const float* W_sem  = (const float*)d_in[2];
    const float* b_sem  = (const float*)d_in[3];
    const float* W_o1   = (const float*)d_in[4];
    const float* g_o1   = (const float*)d_in[5];
    const float* b_o1   = (const float*)d_in[6];
    const float* W_o2   = (const float*)d_in[7];
    const float* g_o2   = (const float*)d_in[8];
    const float* b_o2   = (const float*)d_in[9];
    const float* W_o3   = (const float*)d_in[10];
    const float* W_ci   = (const float*)d_in[11];
    const float* g_ci   = (const float*)d_in[12];
    const float* b_ci   = (const float*)d_in[13];
    const float* W_ctr  = (const float*)d_in[14];
    const float* W_reg  = (const float*)d_in[15];
    const float* W_cls  = (const float*)d_in[16];
    const float* b_cls  = (const float*)d_in[17];
    const float* scales = (const float*)d_in[18];
    float* out = (float*)d_out;

    k_pre<<<36, 256>>>(W_sem, b_sem, W_o1, g_o1, b_o1, W_o2, g_o2, b_o2, W_o3,
                       g_ci, b_ci, W_ctr, W_reg, W_cls);
    k_ab<<<NPTS / 128, 128>>>(coords, feats, out);
    k_c<<<NPTS / 256, 256>>>(feats, W_ci, b_cls, scales, out);
}

// round 16
// speedup vs baseline: 1.1436x; 1.0491x over previous
#include <cuda_runtime.h>
#include <cuda_bf16.h>
#include <math.h>
#include <float.h>

#define NPTS   131072
#define CF     64
#define NCLS   18
#define VOXEL  0.04f
#define SEM_LOGIT (-1.7346010553881064f)
#define OUT_VOFF ((size_t)NCLS * NPTS * 8)

#define AB_BLKS   (NPTS / 128)   // 1024 compute blocks
#define PREP_BLKS 37             // class-table prep blocks appended to k_ab grid

// ---- lane-contiguous per-thread B-fragment images ----
__device__ __align__(16) unsigned WA_SEM[3][32][4], WBz_SEM[3][32][4];
__device__ __align__(16) unsigned WA_1[8][32][4],  WBz_1[8][32][4];
__device__ __align__(16) unsigned WA_2[8][32][4],  WBz_2[8][32][4];
__device__ float2 G1B1[64];
__device__ float2 G2B2[64];
__device__ float2 GCBC[NCLS][64];
__device__ float4 WO3[64];
__device__ float  THR[24];
__device__ __align__(16) float4 HEADW4[NCLS][64][2];
__device__ unsigned g_maskarr[NPTS];

__device__ int g_bmin[3] = {0x7fffffff, 0x7fffffff, 0x7fffffff};
__device__ int g_bmax[3] = {(int)0x80000000, (int)0x80000000, (int)0x80000000};

__device__ __forceinline__ unsigned packbf(float lo, float hi) {
    __nv_bfloat162 p = __floats2bfloat162_rn(lo, hi);
    return *(unsigned*)&p;
}
__device__ __forceinline__ int frag_k(int word, int t) {
    int ks = word >> 1, half = word & 1;
    return 16 * ks + 8 * half + 2 * t;
}

// ---- prep kernel: ONLY what k_ab needs (tiny; 1 iter/thread) ----
__global__ __launch_bounds__(256)
void k_pre(const float* __restrict__ W_sem, const float* __restrict__ b_sem,
           const float* __restrict__ W_o1, const float* __restrict__ g_o1,
           const float* __restrict__ b_o1, const float* __restrict__ W_o2,
           const float* __restrict__ g_o2, const float* __restrict__ b_o2,
           const float* __restrict__ W_o3) {
    int i0 = blockIdx.x * 256 + threadIdx.x;   // 12 blocks * 256 = 3072 threads
    // sem image: 768 elements
    if (i0 < 3 * 256) {
        int i = i0;
        int nb = i >> 8, lane = (i >> 3) & 31, word = i & 7;
        int g = lane >> 2, t = lane & 3, n = nb * 8 + g;
        int k = frag_k(word, t);
        float w0 = (n < NCLS) ? __ldg(W_sem + k * NCLS + n) : 0.0f;
        float w1 = (n < NCLS) ? __ldg(W_sem + (k + 1) * NCLS + n) : 0.0f;
        unsigned v = packbf(w0, w1);
        if (word < 4) WA_SEM[nb][lane][word] = v; else WBz_SEM[nb][lane][word - 4] = v;
    }
    // l1/l2 images: 2048 elements (offset region)
    {
        int i = i0 - 3 * 256;
        if (i >= 0 && i < 8 * 256) {
            int nb = i >> 8, lane = (i >> 3) & 31, word = i & 7;
            int g = lane >> 2, t = lane & 3, n = nb * 8 + g;
            int k = frag_k(word, t);
            unsigned v1 = packbf(__ldg(W_o1 + k * 64 + n), __ldg(W_o1 + (k + 1) * 64 + n));
            unsigned v2 = packbf(__ldg(W_o2 + k * 64 + n), __ldg(W_o2 + (k + 1) * 64 + n));
            if (word < 4) { WA_1[nb][lane][word] = v1; WA_2[nb][lane][word] = v2; }
            else          { WBz_1[nb][lane][word - 4] = v1; WBz_2[nb][lane][word - 4] = v2; }
        }
    }
    // BN params + WO3: 64, THR: 24
    {
        int e = i0 - 11 * 256;
        if (e >= 0 && e < 64) {
            G1B1[e] = make_float2(__ldg(g_o1 + e), __ldg(b_o1 + e));
            G2B2[e] = make_float2(__ldg(g_o2 + e), __ldg(b_o2 + e));
            WO3[e]  = make_float4(__ldg(W_o3 + 3 * e), __ldg(W_o3 + 3 * e + 1),
                                  __ldg(W_o3 + 3 * e + 2), 0.0f);
        }
        int e2 = i0 - 11 * 256 - 64;
        if (e2 >= 0 && e2 < 24)
            THR[e2] = (e2 < NCLS) ? (SEM_LOGIT - __ldg(b_sem + e2)) : FLT_MAX;
    }
}

__device__ __forceinline__ float eluf(float x) { return x > 0.0f ? x : (__expf(x) - 1.0f); }

__device__ __forceinline__ void mma16816(float* c, const unsigned* a, unsigned b0, unsigned b1) {
    asm volatile("mma.sync.aligned.m16n8k16.row.col.f32.bf16.bf16.f32 "
                 "{%0,%1,%2,%3}, {%4,%5,%6,%7}, {%8,%9}, {%0,%1,%2,%3};"
                 : "+f"(c[0]), "+f"(c[1]), "+f"(c[2]), "+f"(c[3])
                 : "r"(a[0]), "r"(a[1]), "r"(a[2]), "r"(a[3]), "r"(b0), "r"(b1));
}
__device__ __forceinline__ void mma_nrow_w(float* c, const unsigned af[4][4], uint4 wa, uint4 wb) {
    mma16816(c, af[0], wa.x, wa.y);
    mma16816(c, af[1], wa.z, wa.w);
    mma16816(c, af[2], wb.x, wb.y);
    mma16816(c, af[3], wb.z, wb.w);
}

#define PITCH 36   // smem row pitch in 4B words (bank = 4g+t, conflict-free frag loads)

// ---- compute kernel: bounds + mask + MLP -> unclipped voted ----
// blocks >= AB_BLKS prepare the per-class tables (needed only by k_c, which
// launches after this whole grid completes -> stream order covers the dep).
__global__ __launch_bounds__(128, 4)
void k_ab(const int* __restrict__ coords, const float* __restrict__ feats,
          const float* __restrict__ g_ci, const float* __restrict__ b_ci,
          const float* __restrict__ W_ctr, const float* __restrict__ W_reg,
          const float* __restrict__ W_cls, float* __restrict__ out)
{
    if (blockIdx.x >= AB_BLKS) {
        // ---- class-table prep (GCBC, HEADW4) ----
        int i0 = (blockIdx.x - AB_BLKS) * 128 + threadIdx.x;
        int stride = PREP_BLKS * 128;   // 4736
        for (int i = i0; i < NCLS * 64; i += stride) {
            int c = i >> 6, e = i & 63;
            GCBC[c][e] = make_float2(__ldg(g_ci + c * CF + e), __ldg(b_ci + c * CF + e));
        }
        for (int i = i0; i < NCLS * 64 * 8; i += stride) {
            int c = i >> 9, r = i & 511;
            int e = r >> 3, j = r & 7;
            float v;
            if (j == 0)      v = __ldg(W_ctr + e);
            else if (j < 7)  v = __ldg(W_reg + e * 6 + (j - 1));
            else             v = __ldg(W_cls + e * NCLS + c);
            ((float*)&HEADW4[c][e][0])[j] = v;
        }
        return;
    }

    __shared__ unsigned s_stage[4][32 * PITCH];
    const int tid  = threadIdx.x;
    const int w    = tid >> 5;
    const int lane = tid & 31;
    const int g    = lane >> 2;
    const int t    = lane & 3;
    const int rb   = blockIdx.x * 128 + w * 32;   // warp covers 32 rows

    // ---- bounds contribution (lane-per-row, warp reduce, global RED) ----
    {
        int4 cr = __ldg((const int4*)coords + rb + lane);
        int l0 = __reduce_min_sync(0xffffffffu, cr.y), h0 = __reduce_max_sync(0xffffffffu, cr.y);
        int l1 = __reduce_min_sync(0xffffffffu, cr.z), h1 = __reduce_max_sync(0xffffffffu, cr.z);
        int l2 = __reduce_min_sync(0xffffffffu, cr.w), h2 = __reduce_max_sync(0xffffffffu, cr.w);
        if (lane == 0) {
            atomicMin(&g_bmin[0], l0); atomicMax(&g_bmax[0], h0);
            atomicMin(&g_bmin[1], l1); atomicMax(&g_bmax[1], h1);
            atomicMin(&g_bmin[2], l2); atomicMax(&g_bmax[2], h2);
        }
    }

    // ---- stage warp's 32 rows -> bf16 smem (coalesced LDG.128) ----
    unsigned* st = s_stage[w];
    {
        const float4* base = (const float4*)(feats + (size_t)rb * CF);
#pragma unroll
        for (int it = 0; it < 16; it++) {
            int i = it * 32 + lane;
            float4 v = __ldg(base + i);
            int r = i >> 4, c = i & 15;
            st[r * PITCH + 2 * c]     = packbf(v.x, v.y);
            st[r * PITCH + 2 * c + 1] = packbf(v.z, v.w);
        }
    }
    __syncwarp();

    // ---- A fragments via conflict-free LDS.32 ----
    unsigned af[2][4][4];
#pragma unroll
    for (int G = 0; G < 2; G++) {
        int ra = (G * 16 + g) * PITCH, rc = (G * 16 + g + 8) * PITCH;
#pragma unroll
        for (int ks = 0; ks < 4; ks++) {
            af[G][ks][0] = st[ra + 8 * ks + t];
            af[G][ks][1] = st[rc + 8 * ks + t];
            af[G][ks][2] = st[ra + 8 * ks + 4 + t];
            af[G][ks][3] = st[rc + 8 * ks + 4 + t];
        }
    }

    // ---- sem GEMM -> mask bits -> g_maskarr ----
    unsigned m[4] = {0u, 0u, 0u, 0u};
#pragma unroll
    for (int nb = 0; nb < 3; nb++) {
        uint4 wa = __ldg((const uint4*)&WA_SEM[nb][lane][0]);
        uint4 wb = __ldg((const uint4*)&WBz_SEM[nb][lane][0]);
        int e0 = nb * 8 + 2 * t;
        float th0 = __ldg(THR + e0), th1 = __ldg(THR + e0 + 1);
#pragma unroll
        for (int G = 0; G < 2; G++) {
            float cs[4] = {0.f, 0.f, 0.f, 0.f};
            mma_nrow_w(cs, af[G], wa, wb);
            if (cs[0] > th0) m[2 * G]     |= 1u << e0;
            if (cs[2] > th0) m[2 * G + 1] |= 1u << e0;
            if (cs[1] > th1) m[2 * G]     |= 1u << (e0 + 1);
            if (cs[3] > th1) m[2 * G + 1] |= 1u << (e0 + 1);
        }
    }
#pragma unroll
    for (int q = 0; q < 4; q++) {
        m[q] |= __shfl_xor_sync(0xffffffffu, m[q], 1);
        m[q] |= __shfl_xor_sync(0xffffffffu, m[q], 2);
    }
    if (t == 0) {
#pragma unroll
        for (int q = 0; q < 4; q++)
            g_maskarr[rb + (q >> 1) * 16 + (q & 1) * 8 + g] = m[q];
    }

    // ---- l1 GEMM + BN/ELU -> l2 A-fragments in registers ----
    unsigned a2[2][4][4];
#pragma unroll
    for (int ks = 0; ks < 4; ks++) {
#pragma unroll
        for (int p = 0; p < 2; p++) {
            int nb = 2 * ks + p;
            uint4 wa = __ldg((const uint4*)&WA_1[nb][lane][0]);
            uint4 wb = __ldg((const uint4*)&WBz_1[nb][lane][0]);
            int e0 = nb * 8 + 2 * t;
            float2 gb0 = __ldg(&G1B1[e0]), gb1 = __ldg(&G1B1[e0 + 1]);
#pragma unroll
            for (int G = 0; G < 2; G++) {
                float c1[4] = {0.f, 0.f, 0.f, 0.f};
                mma_nrow_w(c1, af[G], wa, wb);
                a2[G][ks][2 * p]     = packbf(eluf(fmaf(c1[0], gb0.x, gb0.y)),
                                              eluf(fmaf(c1[1], gb1.x, gb1.y)));
                a2[G][ks][2 * p + 1] = packbf(eluf(fmaf(c1[2], gb0.x, gb0.y)),
                                              eluf(fmaf(c1[3], gb1.x, gb1.y)));
            }
        }
    }

    // ---- l2 GEMM + BN/ELU + l3 dot -> UNCLIPPED voted (clip in k_c) ----
    float ox[4] = {0.f, 0.f, 0.f, 0.f}, oy[4] = {0.f, 0.f, 0.f, 0.f}, oz[4] = {0.f, 0.f, 0.f, 0.f};
#pragma unroll
    for (int nb = 0; nb < 8; nb++) {
        uint4 wa = __ldg((const uint4*)&WA_2[nb][lane][0]);
        uint4 wb = __ldg((const uint4*)&WBz_2[nb][lane][0]);
        int e0 = nb * 8 + 2 * t;
        float2 gb0 = __ldg(&G2B2[e0]), gb1 = __ldg(&G2B2[e0 + 1]);
        float4 w0 = __ldg(&WO3[e0]), w1 = __ldg(&WO3[e0 + 1]);
#pragma unroll
        for (int G = 0; G < 2; G++) {
            float c2[4] = {0.f, 0.f, 0.f, 0.f};
            mma_nrow_w(c2, a2[G], wa, wb);
            float h00 = eluf(fmaf(c2[0], gb0.x, gb0.y)), h01 = eluf(fmaf(c2[1], gb1.x, gb1.y));
            float h10 = eluf(fmaf(c2[2], gb0.x, gb0.y)), h11 = eluf(fmaf(c2[3], gb1.x, gb1.y));
            ox[2 * G]     = fmaf(h00, w0.x, fmaf(h01, w1.x, ox[2 * G]));
            oy[2 * G]     = fmaf(h00, w0.y, fmaf(h01, w1.y, oy[2 * G]));
            oz[2 * G]     = fmaf(h00, w0.z, fmaf(h01, w1.z, oz[2 * G]));
            ox[2 * G + 1] = fmaf(h10, w0.x, fmaf(h11, w1.x, ox[2 * G + 1]));
            oy[2 * G + 1] = fmaf(h10, w0.y, fmaf(h11, w1.y, oy[2 * G + 1]));
            oz[2 * G + 1] = fmaf(h10, w0.z, fmaf(h11, w1.z, oz[2 * G + 1]));
        }
    }
#pragma unroll
    for (int s = 1; s <= 2; s <<= 1) {
#pragma unroll
        for (int q = 0; q < 4; q++) {
            ox[q] += __shfl_xor_sync(0xffffffffu, ox[q], s);
            oy[q] += __shfl_xor_sync(0xffffffffu, oy[q], s);
            oz[q] += __shfl_xor_sync(0xffffffffu, oz[q], s);
        }
    }
    if (t == 0) {
#pragma unroll
        for (int q = 0; q < 4; q++) {
            int r = rb + (q >> 1) * 16 + (q & 1) * 8 + g;
            int4 cr = __ldg((const int4*)coords + r);
            float* vp = out + OUT_VOFF + (size_t)r * 3;
            vp[0] = fmaf((float)cr.y, VOXEL, ox[q]);
            vp[1] = fmaf((float)cr.z, VOXEL, oy[q]);
            vp[2] = fmaf((float)cr.w, VOXEL, oz[q]);
        }
    }
}

// ---- streaming kernel: voted clip + per-class outputs ----
__global__ __launch_bounds__(256, 4)
void k_c(const float* __restrict__ feats, const float* __restrict__ W_ci,
         const float* __restrict__ b_cls, const float* __restrict__ scales,
         float* __restrict__ out)
{
    const int tid  = threadIdx.x;
    const int w    = tid >> 5;
    const int lane = tid & 31;
    const int r0   = blockIdx.x * 256 + w * 32;
    const int row  = r0 + lane;

    // ---- clip voted for this warp's 32 rows (bounds now final) ----
    {
        float mn0 = (float)(g_bmin[0] - 1) * VOXEL, mx0 = (float)(g_bmax[0] + 1) * VOXEL;
        float mn1 = (float)(g_bmin[1] - 1) * VOXEL, mx1 = (float)(g_bmax[1] + 1) * VOXEL;
        float mn2 = (float)(g_bmin[2] - 1) * VOXEL, mx2 = (float)(g_bmax[2] + 1) * VOXEL;
        float* vp = out + OUT_VOFF + (size_t)r0 * 3;
#pragma unroll
        for (int j = 0; j < 3; j++) {
            int idx = j * 32 + lane;
            int dim = idx % 3;
            float v = vp[idx];
            float lo = (dim == 0) ? mn0 : ((dim == 1) ? mn1 : mn2);
            float hi = (dim == 0) ? mx0 : ((dim == 1) ? mx1 : mx2);
            vp[idx] = fminf(fmaxf(v, lo), hi);
        }
    }

    const unsigned mw   = __ldg(g_maskarr + row);
    const unsigned worv = __reduce_or_sync(0xffffffffu, mw);

    for (int c = 0; c < NCLS; c++) {
        float4* base4 = (float4*)(out + ((size_t)c * NPTS + r0) * 8);
        if (!((worv >> c) & 1u)) {
            // warp's 32 rows all masked: feat_c == 0 exactly -> ctr=0, reg=exp(0)=1, cls=b_cls
            float bc = __ldg(b_cls + c);
            float4 v = (lane & 1) ? make_float4(1.0f, 1.0f, 1.0f, bc)
                                  : make_float4(0.0f, 1.0f, 1.0f, 1.0f);
            base4[lane]      = v;
            base4[lane + 32] = v;
            continue;   // warp-uniform branch
        }
        // ---- slow path: exact fp32 SIMT per-row ----
        float o[8];
#pragma unroll
        for (int j = 0; j < 8; j++) o[j] = 0.f;
        if ((mw >> c) & 1u) {
            const float* fr = feats + (size_t)row * CF;
            const float* Wc = W_ci + (size_t)c * 4096;
            for (int ec = 0; ec < 8; ec++) {
                int e0 = ec * 8;
                float acc[8];
#pragma unroll
                for (int j = 0; j < 8; j++) acc[j] = 0.f;
                for (int k = 0; k < CF; k++) {
                    float f = __ldg(fr + k);
                    const float* wk = Wc + k * 64 + e0;
#pragma unroll
                    for (int j = 0; j < 8; j++) acc[j] = fmaf(f, __ldg(wk + j), acc[j]);
                }
#pragma unroll
                for (int j = 0; j < 8; j++) {
                    float2 gb = __ldg(&GCBC[c][e0 + j]);
                    float fc = eluf(fmaf(acc[j], gb.x, gb.y));
                    float4 ha = __ldg(&HEADW4[c][e0 + j][0]);
                    float4 hb = __ldg(&HEADW4[c][e0 + j][1]);
                    o[0] = fmaf(fc, ha.x, o[0]); o[1] = fmaf(fc, ha.y, o[1]);
                    o[2] = fmaf(fc, ha.z, o[2]); o[3] = fmaf(fc, ha.w, o[3]);
                    o[4] = fmaf(fc, hb.x, o[4]); o[5] = fmaf(fc, hb.y, o[5]);
                    o[6] = fmaf(fc, hb.z, o[6]); o[7] = fmaf(fc, hb.w, o[7]);
                }
            }
        }
        float sc = __ldg(scales + c), bc = __ldg(b_cls + c);
        float* p = out + ((size_t)c * NPTS + row) * 8;
        *(float4*)(p)     = make_float4(o[0], __expf(o[1] * sc),
                                        __expf(o[2] * sc), __expf(o[3] * sc));
        *(float4*)(p + 4) = make_float4(__expf(o[4] * sc), __expf(o[5] * sc),
                                        __expf(o[6] * sc), o[7] + bc);
    }
}

extern "C" void kernel_launch(void* const* d_in, const int* in_sizes, int n_in,
                              void* d_out, int out_size) {
    const int*   coords = (const int*)d_in[0];
    const float* feats  = (const float*)d_in[1];
    const float* W_sem  = (const float*)d_in[2];
    const float* b_sem  = (const float*)d_in[3];
    const float* W_o1   = (const float*)d_in[4];
    const float* g_o1   = (const float*)d_in[5];
    const float* b_o1   = (const float*)d_in[6];
    const float* W_o2   = (const float*)d_in[7];
    const float* g_o2   = (const float*)d_in[8];
    const float* b_o2   = (const float*)d_in[9];
    const float* W_o3   = (const float*)d_in[10];
    const float* W_ci   = (const float*)d_in[11];
    const float* g_ci   = (const float*)d_in[12];
    const float* b_ci   = (const float*)d_in[13];
    const float* W_ctr  = (const float*)d_in[14];
    const float* W_reg  = (const float*)d_in[15];
    const float* W_cls  = (const float*)d_in[16];
    const float* b_cls  = (const float*)d_in[17];
    const float* scales = (const float*)d_in[18];
    float* out = (float*)d_out;

    k_pre<<<12, 256>>>(W_sem, b_sem, W_o1, g_o1, b_o1, W_o2, g_o2, b_o2, W_o3);
    k_ab<<<AB_BLKS + PREP_BLKS, 128>>>(coords, feats, g_ci, b_ci,
                                       W_ctr, W_reg, W_cls, out);
    k_c<<<NPTS / 256, 256>>>(feats, W_ci, b_cls, scales, out);
}